// round 16
// baseline (speedup 1.0000x reference)
#include <cuda_runtime.h>
#include <cuda_bf16.h>
#include <stdint.h>

// ---------------- problem constants (fixed shapes) ----------------
#define DD   128
#define HH   192
#define WP   193            // pred_z last-dim
#define WW   192            // d last-dim (WP-1)
#define TOTD (DD*HH*WW)     // 4,718,592
#define N0   (DD*HH)        // 24,576 first-slice elements
#define RANK ((N0-1)/2)     // 12,287 (lower median, 0-based)
#define NBIN 4096           // radix bins (top 12 bits of sortable key)
#define NBLK 2304           // total blocks (6 x 48 x 8)

// ---------------- device scratch (no allocations allowed) ----------------
__device__ double   g_sum;              // sum of (d-med)^2
__device__ unsigned g_mon;              // float bits of max(relu(1-dz))
__device__ int      g_hist[NBIN];       // radix histogram (top 12 bits of key)
__device__ unsigned g_z0[N0];           // staged sortable keys of first-slice values
__device__ unsigned g_cand[N0];         // candidate keys
__device__ int      g_ccount;
__device__ unsigned g_count;            // finished-block counter (last-block pattern)

// ---------------- helpers ----------------
__device__ __forceinline__ int refl(int i, int n) {
    return (i < 0) ? -i : ((i >= n) ? (2*n - 2 - i) : i);
}

__device__ __forceinline__ unsigned f2key(float f) {
    unsigned u = __float_as_uint(f);
    return (u & 0x80000000u) ? ~u : (u | 0x80000000u);
}
__device__ __forceinline__ float key2f(unsigned k) {
    unsigned u = (k & 0x80000000u) ? (k & 0x7fffffffu) : ~k;
    return __uint_as_float(u);
}

__device__ __forceinline__ void ce(float& a, float& b) {
    float mn = fminf(a, b);
    float mx = fmaxf(a, b);
    a = mn; b = mx;
}

// ---------- sorting / merging networks (Batcher odd-even) ----------
__device__ __forceinline__ void sort3(float&a,float&b,float&c){ ce(a,b); ce(a,c); ce(b,c); }
__device__ __forceinline__ void sort4(float&a,float&b,float&c,float&d){
    ce(a,b); ce(c,d); ce(a,c); ce(b,d); ce(b,c);
}
__device__ __forceinline__ void merge12(float a0,float b0,float b1,float z[3]){
    float v0=fminf(a0,b0), v1=fmaxf(a0,b0);
    z[0]=v0; z[1]=fminf(b1,v1); z[2]=fmaxf(b1,v1);
}
__device__ __forceinline__ void merge22(float a0,float a1,float b0,float b1,float z[4]){
    float v0=fminf(a0,b0), v1=fmaxf(a0,b0);
    float w0=fminf(a1,b1), w1=fmaxf(a1,b1);
    z[0]=v0; z[1]=fminf(w0,v1); z[2]=fmaxf(w0,v1); z[3]=w1;
}
__device__ __forceinline__ void merge23(float a0,float a1,float b0,float b1,float b2,float z[5]){
    float v[3]; merge12(a0,b0,b2,v);
    float w0=fminf(a1,b1), w1=fmaxf(a1,b1);
    z[0]=v[0];
    z[1]=fminf(w0,v[1]); z[2]=fmaxf(w0,v[1]);
    z[3]=fminf(w1,v[2]); z[4]=fmaxf(w1,v[2]);
}
__device__ __forceinline__ void merge33(float a0,float a1,float a2,float b0,float b1,float b2,float z[6]){
    float v[4]; merge22(a0,a2,b0,b2,v);
    float w0=fminf(a1,b1), w1=fmaxf(a1,b1);
    z[0]=v[0];
    z[1]=fminf(w0,v[1]); z[2]=fmaxf(w0,v[1]);
    z[3]=fminf(w1,v[2]); z[4]=fmaxf(w1,v[2]);
    z[5]=v[3];
}
__device__ __forceinline__ void merge44(float a0,float a1,float a2,float a3,
                                        float b0,float b1,float b2,float b3,float z[8]){
    float v[4]; merge22(a0,a2,b0,b2,v);
    float w[4]; merge22(a1,a3,b1,b3,w);
    z[0]=v[0];
    z[1]=fminf(w[0],v[1]); z[2]=fmaxf(w[0],v[1]);
    z[3]=fminf(w[1],v[2]); z[4]=fmaxf(w[1],v[2]);
    z[5]=fminf(w[2],v[3]); z[6]=fmaxf(w[2],v[3]);
    z[7]=w[3];
}
__device__ __forceinline__ void merge45(float a0,float a1,float a2,float a3,
                                        float b0,float b1,float b2,float b3,float b4,float z[9]){
    float v[5]; merge23(a0,a2,b0,b2,b4,v);
    float w[4]; merge22(a1,a3,b1,b3,w);
    z[0]=v[0];
    z[1]=fminf(w[0],v[1]); z[2]=fmaxf(w[0],v[1]);
    z[3]=fminf(w[1],v[2]); z[4]=fmaxf(w[1],v[2]);
    z[5]=fminf(w[2],v[3]); z[6]=fmaxf(w[2],v[3]);
    z[7]=fminf(w[3],v[4]); z[8]=fmaxf(w[3],v[4]);
}
__device__ __forceinline__ void merge55(float a0,float a1,float a2,float a3,float a4,
                                        float b0,float b1,float b2,float b3,float b4,float z[10]){
    float v[6]; merge33(a0,a2,a4,b0,b2,b4,v);
    float w[4]; merge22(a1,a3,b1,b3,w);
    z[0]=v[0];
    z[1]=fminf(w[0],v[1]); z[2]=fmaxf(w[0],v[1]);
    z[3]=fminf(w[1],v[2]); z[4]=fmaxf(w[1],v[2]);
    z[5]=fminf(w[2],v[3]); z[6]=fmaxf(w[2],v[3]);
    z[7]=fminf(w[3],v[4]); z[8]=fmaxf(w[3],v[4]);
    z[9]=v[5];
}

// in-place sort of 9 (odd-even mergesort: 26 CE)
__device__ __forceinline__ void sort9(float p[9]){
    sort4(p[0],p[1],p[2],p[3]);
    ce(p[4],p[5]);
    sort3(p[6],p[7],p[8]);
    { float q[5]; merge23(p[4],p[5],p[6],p[7],p[8],q);
      p[4]=q[0]; p[5]=q[1]; p[6]=q[2]; p[7]=q[3]; p[8]=q[4]; }
    float s[9]; merge45(p[0],p[1],p[2],p[3],p[4],p[5],p[6],p[7],p[8],s);
#pragma unroll
    for(int i=0;i<9;i++) p[i]=s[i];
}

// middle outputs z[4..13] of odd-even merge(9,9) of sorted A, B  -> mid[0..9]
__device__ __forceinline__ void merge99_mid(const float A[9], const float B[9], float mid[10]){
    float v[10], w[8];
    merge55(A[0],A[2],A[4],A[6],A[8], B[0],B[2],B[4],B[6],B[8], v);
    merge44(A[1],A[3],A[5],A[7],      B[1],B[3],B[5],B[7],      w);
    mid[0]=fmaxf(w[1],v[2]);                          // z4
    mid[1]=fminf(w[2],v[3]); mid[2]=fmaxf(w[2],v[3]); // z5,z6
    mid[3]=fminf(w[3],v[4]); mid[4]=fmaxf(w[3],v[4]); // z7,z8
    mid[5]=fminf(w[4],v[5]); mid[6]=fmaxf(w[4],v[5]); // z9,z10
    mid[7]=fminf(w[5],v[6]); mid[8]=fmaxf(w[5],v[6]); // z11,z12
    mid[9]=fminf(w[6],v[7]);                          // z13
}

// rank-13 (0-based) of 27 = 14th smallest of sorted-18 (mid=z[4..13]) u sorted-9 C
// symmetric in WHICH two planes were merged; C is the remaining plane.
__device__ __forceinline__ float select13(const float mid[10], const float C[9]){
    float t0 = fminf(fmaxf(mid[0],C[8]), fmaxf(mid[1],C[7]));
    float t1 = fminf(fmaxf(mid[2],C[6]), fmaxf(mid[3],C[5]));
    float t2 = fminf(fmaxf(mid[4],C[4]), fmaxf(mid[5],C[3]));
    float t3 = fminf(fmaxf(mid[6],C[2]), fmaxf(mid[7],C[1]));
    float t4 = fminf(fmaxf(mid[8],C[0]), mid[9]);
    return fminf(fminf(fminf(t0,t1), fminf(t2,t3)), t4);
}

// ---------------- post phase (runs in the LAST-finishing block, 128 threads) -----------
__device__ __noinline__ void post_phase(float* __restrict__ out, int tid){
    __shared__ int wsum[4];
    __shared__ int sb[2];
    const int lane = tid & 31;
    const int wrp  = tid >> 5;

    __threadfence();   // make all other blocks' fenced writes visible

    // pass 1: each thread sums its 32 bins (8 x int4), no bins kept live
    const int4* h4 = (const int4*)g_hist;
    int local = 0;
#pragma unroll
    for (int g = 0; g < 8; g++){
        int4 h = h4[tid*8 + g];
        local += h.x + h.y + h.z + h.w;
    }
    // block-wide exclusive prefix over thread sums (4 warps)
    int v = local;
#pragma unroll
    for (int off = 1; off < 32; off <<= 1){
        int u = __shfl_up_sync(0xffffffffu, v, off);
        if (lane >= off) v += u;
    }
    if (lane == 31) wsum[wrp] = v;
    __syncthreads();
    int wpre = 0;
#pragma unroll
    for (int w = 0; w < 4; w++) wpre += (w < wrp) ? wsum[w] : 0;
    int e = wpre + v - local;          // exclusive prefix of this thread's first bin
    // pass 2: walk own 32 bins to locate RANK
    if (e <= RANK && RANK < e + local){
#pragma unroll
        for (int g = 0; g < 8; g++){
            int4 h = h4[tid*8 + g];
            int hh[4] = {h.x, h.y, h.z, h.w};
#pragma unroll
            for (int q = 0; q < 4; q++){
                if (e <= RANK && RANK < e + hh[q]){ sb[0] = tid*32 + g*4 + q; sb[1] = RANK - e; }
                e += hh[q];
            }
        }
    }
    __syncthreads();
    const int bkt = sb[0];

    // gather candidates (vectorized; all loads L2-hot)
    const uint4* z4 = (const uint4*)g_z0;
#pragma unroll 4
    for (int i = tid; i < N0/4; i += 128){
        uint4 k = z4[i];
        if ((int)(k.x >> 20) == bkt) g_cand[atomicAdd(&g_ccount,1)] = k.x;
        if ((int)(k.y >> 20) == bkt) g_cand[atomicAdd(&g_ccount,1)] = k.y;
        if ((int)(k.z >> 20) == bkt) g_cand[atomicAdd(&g_ccount,1)] = k.z;
        if ((int)(k.w >> 20) == bkt) g_cand[atomicAdd(&g_ccount,1)] = k.w;
    }
    __syncthreads();
    const int m = g_ccount;
    const int r = sb[1];
    for (int i = tid; i < m; i += 128){
        unsigned ki = g_cand[i];
        int less = 0, eq = 0;
        for (int j = 0; j < m; j++){
            unsigned kj = g_cand[j];
            less += (kj < ki);
            eq   += (kj == ki);
        }
        if (less <= r && r < less + eq){
            float val = key2f(ki);
            out[2] = val*val;                     // loss_average
        }
    }
    __syncthreads();
    if (tid == 0){
        out[0] = (float)(g_sum * (1.0/(double)TOTD));  // loss_smooth
        out[1] = __uint_as_float(g_mon);               // loss_mon
        g_sum = 0.0; g_mon = 0u; g_ccount = 0; g_count = 0u;  // reset for next replay
    }
    // reset histogram (32 bins per thread)
    int4* h4w = (int4*)g_hist;
    const int4 zz = make_int4(0,0,0,0);
#pragma unroll
    for (int g = 0; g < 8; g++) h4w[tid*8 + g] = zz;
}

// ---------------- fused kernel: diff + mon + median + hist + residuals + post ----------
// Shared-merge scheme (one merge99_mid serves two windows); ZC=16 so the grid has
// 2304 small blocks -> fine-grained packing at 7 blocks/SM (no wave quantization).
#define TX 32
#define TY 4
#define ZC 16
__global__ __launch_bounds__(TX*TY) void k_median(const float* __restrict__ p,
                                                  float* __restrict__ out){
    __shared__ float sm[2][TY+2][TX+2];
    const int tx = threadIdx.x, ty = threadIdx.y;
    const int tid = ty*TX + tx;
    const int gx0 = blockIdx.x*TX;
    const int gy0 = blockIdx.y*TY;
    const int z0  = blockIdx.z*ZC;

    // ---- fused first-slice key staging + histogram (first 192 blocks) ----
    {
        int b = blockIdx.x + 6*(blockIdx.y + 48*blockIdx.z);
        if (b < 192){
            int i = b*128 + tid;                       // covers N0 exactly
            unsigned key = f2key(p[(size_t)i * WP]);
            g_z0[i] = key;
            atomicAdd(&g_hist[key >> 20], 1);          // 12-bit radix
        }
    }

    // stage one z-plane of d (reflect in y,x) into smem buffer `buf`
    auto load_plane = [&](int z, int buf){
        const int zr = refl(z, DD);
        const float* base = p + (size_t)zr * HH * WP;
        {
            int idx = tid;
            int yy = idx/(TX+2), xx = idx%(TX+2);
            int gy = refl(gy0-1+yy, HH);
            int gx = refl(gx0-1+xx, WW);
            const float* r = base + (size_t)gy*WP + gx;
            sm[buf][yy][xx] = r[1] - r[0];
        }
        {
            int idx = tid + TX*TY;
            if (idx < (TY+2)*(TX+2)){
                int yy = idx/(TX+2), xx = idx%(TX+2);
                int gy = refl(gy0-1+yy, HH);
                int gx = refl(gx0-1+xx, WW);
                const float* r = base + (size_t)gy*WP + gx;
                sm[buf][yy][xx] = r[1] - r[0];
            }
        }
    };
    auto read9 = [&](int buf, float q[9], float& ctr){
#pragma unroll
        for(int j=0;j<9;j++) q[j] = sm[buf][ty + j/3][tx + j%3];
        ctr = q[4];
    };

    float Cm[9], Sk[9], M[10];
    float XA[9], YA[9], XB[9], YB[9], MB[10];
    float c0, c1, dum;
    float lsum = 0.0f, lmax = 0.0f;

    auto acc = [&](float med, float ctr){
        float diff = ctr - med;
        lsum += diff*diff;
        lmax  = fmaxf(lmax, 1.0f - ctr);
    };

    // prologue: Cm = sorted(z0-1), M = merge(z0, z0+1), Sk = sorted(z0+1)
    load_plane(z0-1, 0); __syncthreads(); read9(0, Cm, dum); sort9(Cm);
    load_plane(z0,   1); __syncthreads(); read9(1, XA, c0);  sort9(XA);
    load_plane(z0+1, 0); __syncthreads(); read9(0, Sk, c1);  sort9(Sk);
    merge99_mid(XA, Sk, M);

#pragma unroll 1
    for(int zi = 0; zi < ZC; zi += 4){
        const int z = z0 + zi;
        // ---- pair A: windows z, z+1 (shared merge M) ----
        acc(select13(M, Cm), c0);
        load_plane(z+2, 1); __syncthreads(); read9(1, XA, c0); sort9(XA);
        acc(select13(M, XA), c1);
        load_plane(z+3, 0); __syncthreads(); read9(0, YA, c1); sort9(YA);
        merge99_mid(XA, YA, MB);

        // ---- pair B: windows z+2, z+3 (shared merge MB) ----
        acc(select13(MB, Sk), c0);
        load_plane(z+4, 1); __syncthreads(); read9(1, XB, c0); sort9(XB);
        acc(select13(MB, XB), c1);
        if (zi + 4 < ZC){
            load_plane(z+5, 0); __syncthreads(); read9(0, YB, c1); sort9(YB);
            merge99_mid(XB, YB, M);
#pragma unroll
            for(int j=0;j<9;j++){ Cm[j] = YA[j]; Sk[j] = YB[j]; }
        }
    }

    // block reduction
#pragma unroll
    for(int off = 16; off; off >>= 1){
        lsum += __shfl_xor_sync(0xffffffffu, lsum, off);
        lmax  = fmaxf(lmax, __shfl_xor_sync(0xffffffffu, lmax, off));
    }
    __shared__ float rs[TY], rm[TY];
    __shared__ unsigned s_rank;
    if ((tid & 31) == 0){ rs[tid>>5] = lsum; rm[tid>>5] = lmax; }
    __syncthreads();
    if (tid == 0){
        float s = rs[0]+rs[1]+rs[2]+rs[3];
        float m = fmaxf(fmaxf(rm[0], rm[1]), fmaxf(rm[2], rm[3]));
        atomicAdd(&g_sum, (double)s);
        atomicMax(&g_mon, __float_as_uint(m));   // m >= 0 always (lmax init 0)
        __threadfence();                          // publish before signaling done
        s_rank = atomicAdd(&g_count, 1u);
    }
    __syncthreads();

    // last-finishing block runs the post phase
    if (s_rank == NBLK - 1){
        post_phase(out, tid);
    }
}

// ---------------- launch ----------------
extern "C" void kernel_launch(void* const* d_in, const int* in_sizes, int n_in,
                              void* d_out, int out_size) {
    const float* p = (const float*)d_in[0];
    float* out = (float*)d_out;

    dim3 grid(WW/TX, HH/TY, DD/ZC);   // 6 x 48 x 8 = 2304 blocks
    dim3 block(TX, TY);
    k_median<<<grid, block>>>(p, out);
}

// round 17
// speedup vs baseline: 2.0245x; 2.0245x over previous
#include <cuda_runtime.h>
#include <cuda_bf16.h>
#include <stdint.h>

// ---------------- problem constants (fixed shapes) ----------------
#define DD   128
#define HH   192
#define WP   193            // pred_z last-dim
#define WW   192            // d last-dim (WP-1)
#define TOTD (DD*HH*WW)     // 4,718,592
#define N0   (DD*HH)        // 24,576 first-slice elements
#define RANK ((N0-1)/2)     // 12,287 (lower median, 0-based)
#define NBIN 4096           // radix bins (top 12 bits of sortable key)

// ---------------- device scratch (no allocations allowed) ----------------
__device__ double   g_sum;              // sum of (d-med)^2
__device__ unsigned g_mon;              // float bits of max(relu(1-dz))
__device__ int      g_hist[NBIN];       // radix histogram (top 12 bits of key)
__device__ unsigned g_z0[N0];           // staged sortable keys of first-slice values
__device__ unsigned g_cand[N0];         // candidate keys
__device__ int      g_ccount;

// ---------------- helpers ----------------
__device__ __forceinline__ int refl(int i, int n) {
    return (i < 0) ? -i : ((i >= n) ? (2*n - 2 - i) : i);
}

__device__ __forceinline__ unsigned f2key(float f) {
    unsigned u = __float_as_uint(f);
    return (u & 0x80000000u) ? ~u : (u | 0x80000000u);
}
__device__ __forceinline__ float key2f(unsigned k) {
    unsigned u = (k & 0x80000000u) ? (k & 0x7fffffffu) : ~k;
    return __uint_as_float(u);
}

__device__ __forceinline__ void ce(float& a, float& b) {
    float mn = fminf(a, b);
    float mx = fmaxf(a, b);
    a = mn; b = mx;
}

// ---------- sorting / merging networks (Batcher odd-even) ----------
__device__ __forceinline__ void sort3(float&a,float&b,float&c){ ce(a,b); ce(a,c); ce(b,c); }
__device__ __forceinline__ void sort4(float&a,float&b,float&c,float&d){
    ce(a,b); ce(c,d); ce(a,c); ce(b,d); ce(b,c);
}
__device__ __forceinline__ void merge12(float a0,float b0,float b1,float z[3]){
    float v0=fminf(a0,b0), v1=fmaxf(a0,b0);
    z[0]=v0; z[1]=fminf(b1,v1); z[2]=fmaxf(b1,v1);
}
__device__ __forceinline__ void merge22(float a0,float a1,float b0,float b1,float z[4]){
    float v0=fminf(a0,b0), v1=fmaxf(a0,b0);
    float w0=fminf(a1,b1), w1=fmaxf(a1,b1);
    z[0]=v0; z[1]=fminf(w0,v1); z[2]=fmaxf(w0,v1); z[3]=w1;
}
__device__ __forceinline__ void merge23(float a0,float a1,float b0,float b1,float b2,float z[5]){
    float v[3]; merge12(a0,b0,b2,v);
    float w0=fminf(a1,b1), w1=fmaxf(a1,b1);
    z[0]=v[0];
    z[1]=fminf(w0,v[1]); z[2]=fmaxf(w0,v[1]);
    z[3]=fminf(w1,v[2]); z[4]=fmaxf(w1,v[2]);
}
__device__ __forceinline__ void merge33(float a0,float a1,float a2,float b0,float b1,float b2,float z[6]){
    float v[4]; merge22(a0,a2,b0,b2,v);
    float w0=fminf(a1,b1), w1=fmaxf(a1,b1);
    z[0]=v[0];
    z[1]=fminf(w0,v[1]); z[2]=fmaxf(w0,v[1]);
    z[3]=fminf(w1,v[2]); z[4]=fmaxf(w1,v[2]);
    z[5]=v[3];
}
__device__ __forceinline__ void merge44(float a0,float a1,float a2,float a3,
                                        float b0,float b1,float b2,float b3,float z[8]){
    float v[4]; merge22(a0,a2,b0,b2,v);
    float w[4]; merge22(a1,a3,b1,b3,w);
    z[0]=v[0];
    z[1]=fminf(w[0],v[1]); z[2]=fmaxf(w[0],v[1]);
    z[3]=fminf(w[1],v[2]); z[4]=fmaxf(w[1],v[2]);
    z[5]=fminf(w[2],v[3]); z[6]=fmaxf(w[2],v[3]);
    z[7]=w[3];
}
__device__ __forceinline__ void merge45(float a0,float a1,float a2,float a3,
                                        float b0,float b1,float b2,float b3,float b4,float z[9]){
    float v[5]; merge23(a0,a2,b0,b2,b4,v);
    float w[4]; merge22(a1,a3,b1,b3,w);
    z[0]=v[0];
    z[1]=fminf(w[0],v[1]); z[2]=fmaxf(w[0],v[1]);
    z[3]=fminf(w[1],v[2]); z[4]=fmaxf(w[1],v[2]);
    z[5]=fminf(w[2],v[3]); z[6]=fmaxf(w[2],v[3]);
    z[7]=fminf(w[3],v[4]); z[8]=fmaxf(w[3],v[4]);
}
__device__ __forceinline__ void merge55(float a0,float a1,float a2,float a3,float a4,
                                        float b0,float b1,float b2,float b3,float b4,float z[10]){
    float v[6]; merge33(a0,a2,a4,b0,b2,b4,v);
    float w[4]; merge22(a1,a3,b1,b3,w);
    z[0]=v[0];
    z[1]=fminf(w[0],v[1]); z[2]=fmaxf(w[0],v[1]);
    z[3]=fminf(w[1],v[2]); z[4]=fmaxf(w[1],v[2]);
    z[5]=fminf(w[2],v[3]); z[6]=fmaxf(w[2],v[3]);
    z[7]=fminf(w[3],v[4]); z[8]=fmaxf(w[3],v[4]);
    z[9]=v[5];
}

// in-place sort of 9 (odd-even mergesort: 26 CE)
__device__ __forceinline__ void sort9(float p[9]){
    sort4(p[0],p[1],p[2],p[3]);
    ce(p[4],p[5]);
    sort3(p[6],p[7],p[8]);
    { float q[5]; merge23(p[4],p[5],p[6],p[7],p[8],q);
      p[4]=q[0]; p[5]=q[1]; p[6]=q[2]; p[7]=q[3]; p[8]=q[4]; }
    float s[9]; merge45(p[0],p[1],p[2],p[3],p[4],p[5],p[6],p[7],p[8],s);
#pragma unroll
    for(int i=0;i<9;i++) p[i]=s[i];
}

// middle outputs z[4..13] of odd-even merge(9,9) of sorted A, B  -> mid[0..9]
__device__ __forceinline__ void merge99_mid(const float A[9], const float B[9], float mid[10]){
    float v[10], w[8];
    merge55(A[0],A[2],A[4],A[6],A[8], B[0],B[2],B[4],B[6],B[8], v);
    merge44(A[1],A[3],A[5],A[7],      B[1],B[3],B[5],B[7],      w);
    mid[0]=fmaxf(w[1],v[2]);                          // z4
    mid[1]=fminf(w[2],v[3]); mid[2]=fmaxf(w[2],v[3]); // z5,z6
    mid[3]=fminf(w[3],v[4]); mid[4]=fmaxf(w[3],v[4]); // z7,z8
    mid[5]=fminf(w[4],v[5]); mid[6]=fmaxf(w[4],v[5]); // z9,z10
    mid[7]=fminf(w[5],v[6]); mid[8]=fmaxf(w[5],v[6]); // z11,z12
    mid[9]=fminf(w[6],v[7]);                          // z13
}

// rank-13 (0-based) of 27 = 14th smallest of sorted-18 (mid=z[4..13]) u sorted-9 C
// symmetric in WHICH two planes were merged; C is the remaining plane.
__device__ __forceinline__ float select13(const float mid[10], const float C[9]){
    float t0 = fminf(fmaxf(mid[0],C[8]), fmaxf(mid[1],C[7]));
    float t1 = fminf(fmaxf(mid[2],C[6]), fmaxf(mid[3],C[5]));
    float t2 = fminf(fmaxf(mid[4],C[4]), fmaxf(mid[5],C[3]));
    float t3 = fminf(fmaxf(mid[6],C[2]), fmaxf(mid[7],C[1]));
    float t4 = fminf(fmaxf(mid[8],C[0]), mid[9]);
    return fminf(fminf(fminf(t0,t1), fminf(t2,t3)), t4);
}

// ---------------- median kernel (fused diff + mon + median + hist + residual sum) ------
// Shared-merge scheme: one merge99_mid serves TWO consecutive windows:
//   window z   = select13(merge(z,z+1), sorted(z-1))
//   window z+1 = select13(merge(z,z+1), sorted(z+2))
// NO device-function calls anywhere on the hot path (ABI calls force spills - R15/R16).
#define TX 32
#define TY 4
#define ZC 16
__global__ __launch_bounds__(TX*TY) void k_median(const float* __restrict__ p){
    __shared__ float sm[2][TY+2][TX+2];
    const int tx = threadIdx.x, ty = threadIdx.y;
    const int tid = ty*TX + tx;
    const int gx0 = blockIdx.x*TX;
    const int gy0 = blockIdx.y*TY;
    const int z0  = blockIdx.z*ZC;

    // ---- fused first-slice key staging + histogram (first 192 blocks) ----
    {
        int b = blockIdx.x + 6*(blockIdx.y + 48*blockIdx.z);
        if (b < 192){
            int i = b*128 + tid;                       // covers N0 exactly
            unsigned key = f2key(p[(size_t)i * WP]);
            g_z0[i] = key;
            atomicAdd(&g_hist[key >> 20], 1);          // 12-bit radix
        }
    }

    // ---- hoisted halo-load addressing (z-invariant y/x reflection) ----
    // each thread stages up to 2 of the (TY+2)*(TX+2)=204 halo cells per plane
    int yy0 = tid/(TX+2), xx0 = tid%(TX+2);
    const int so0 = yy0*(TX+2) + xx0;
    const int go0 = refl(gy0-1+yy0, HH)*WP + refl(gx0-1+xx0, WW);
    const int i1  = tid + TX*TY;
    const bool has1 = i1 < (TY+2)*(TX+2);
    int yy1 = i1/(TX+2), xx1 = i1%(TX+2);
    const int so1 = yy1*(TX+2) + xx1;
    const int go1 = refl(gy0-1+yy1, HH)*WP + refl(gx0-1+xx1, WW);

    auto load_plane = [&](int z, int buf){
        const float* base = p + (size_t)refl(z, DD) * (HH*WP);
        float* s = &sm[buf][0][0];
        const float* r0 = base + go0;
        s[so0] = r0[1] - r0[0];
        if (has1){
            const float* r1 = base + go1;
            s[so1] = r1[1] - r1[0];
        }
    };
    auto read9 = [&](int buf, float q[9], float& ctr){
#pragma unroll
        for(int j=0;j<9;j++) q[j] = sm[buf][ty + j/3][tx + j%3];
        ctr = q[4];
    };

    float Cm[9], Sk[9], M[10];
    float XA[9], YA[9], XB[9], YB[9], MB[10];
    float c0, c1, dum;
    float lsum = 0.0f, lmax = 0.0f;

    auto acc = [&](float med, float ctr){
        float diff = ctr - med;
        lsum += diff*diff;
        lmax  = fmaxf(lmax, 1.0f - ctr);
    };

    // prologue: Cm = sorted(z0-1), M = merge(z0, z0+1), Sk = sorted(z0+1)
    load_plane(z0-1, 0); __syncthreads(); read9(0, Cm, dum); sort9(Cm);
    load_plane(z0,   1); __syncthreads(); read9(1, XA, c0);  sort9(XA);
    load_plane(z0+1, 0); __syncthreads(); read9(0, Sk, c1);  sort9(Sk);
    merge99_mid(XA, Sk, M);

#pragma unroll 1
    for(int zi = 0; zi < ZC; zi += 4){
        const int z = z0 + zi;
        // ---- pair A: windows z, z+1 (shared merge M) ----
        acc(select13(M, Cm), c0);
        load_plane(z+2, 1); __syncthreads(); read9(1, XA, c0); sort9(XA);
        acc(select13(M, XA), c1);
        load_plane(z+3, 0); __syncthreads(); read9(0, YA, c1); sort9(YA);
        merge99_mid(XA, YA, MB);

        // ---- pair B: windows z+2, z+3 (shared merge MB) ----
        acc(select13(MB, Sk), c0);
        load_plane(z+4, 1); __syncthreads(); read9(1, XB, c0); sort9(XB);
        acc(select13(MB, XB), c1);
        if (zi + 4 < ZC){
            load_plane(z+5, 0); __syncthreads(); read9(0, YB, c1); sort9(YB);
            merge99_mid(XB, YB, M);
#pragma unroll
            for(int j=0;j<9;j++){ Cm[j] = YA[j]; Sk[j] = YB[j]; }
        }
    }

    // block reduction
#pragma unroll
    for(int off = 16; off; off >>= 1){
        lsum += __shfl_xor_sync(0xffffffffu, lsum, off);
        lmax  = fmaxf(lmax, __shfl_xor_sync(0xffffffffu, lmax, off));
    }
    __shared__ float rs[TY], rm[TY];
    if ((tid & 31) == 0){ rs[tid>>5] = lsum; rm[tid>>5] = lmax; }
    __syncthreads();
    if (tid == 0){
        float s = rs[0]+rs[1]+rs[2]+rs[3];
        float m = fmaxf(fmaxf(rm[0], rm[1]), fmaxf(rm[2], rm[3]));
        atomicAdd(&g_sum, (double)s);
        atomicMax(&g_mon, __float_as_uint(m));   // m >= 0 always (lmax init 0)
    }
}

// ---------------- scan + gather + select + finalize + reset (single block) --------------
__global__ void k_post(float* __restrict__ out){
    __shared__ int wsum[32];
    __shared__ int sb[2];
    const int t    = threadIdx.x;          // 0..1023
    const int lane = t & 31;
    const int wrp  = t >> 5;

    // each thread owns 4 consecutive bins; block-wide scan over thread sums
    int h0 = g_hist[4*t+0], h1 = g_hist[4*t+1], h2 = g_hist[4*t+2], h3 = g_hist[4*t+3];
    int local = h0 + h1 + h2 + h3;
    int v = local;
#pragma unroll
    for (int off = 1; off < 32; off <<= 1){
        int u = __shfl_up_sync(0xffffffffu, v, off);
        if (lane >= off) v += u;
    }
    if (lane == 31) wsum[wrp] = v;
    __syncthreads();
    if (wrp == 0){
        int s = wsum[lane];
#pragma unroll
        for (int off = 1; off < 32; off <<= 1){
            int u = __shfl_up_sync(0xffffffffu, s, off);
            if (lane >= off) s += u;
        }
        wsum[lane] = s;
    }
    __syncthreads();
    int excl = v - local + (wrp ? wsum[wrp-1] : 0);   // exclusive prefix of bin 4t
    int e0 = excl, e1 = e0 + h0, e2 = e1 + h1, e3 = e2 + h2, e4 = e3 + h3;
    if (e0 <= RANK && RANK < e1){ sb[0] = 4*t+0; sb[1] = RANK - e0; }
    if (e1 <= RANK && RANK < e2){ sb[0] = 4*t+1; sb[1] = RANK - e1; }
    if (e2 <= RANK && RANK < e3){ sb[0] = 4*t+2; sb[1] = RANK - e2; }
    if (e3 <= RANK && RANK < e4){ sb[0] = 4*t+3; sb[1] = RANK - e3; }
    __syncthreads();
    const int bkt = sb[0];

    // gather: fully unrolled (24 iterations) -> all loads in flight at once (MLP)
    unsigned keys[N0/1024];
#pragma unroll
    for (int k = 0; k < N0/1024; k++) keys[k] = g_z0[t + k*1024];
#pragma unroll
    for (int k = 0; k < N0/1024; k++){
        if ((int)(keys[k] >> 20) == bkt){
            int pos = atomicAdd(&g_ccount, 1);
            g_cand[pos] = keys[k];
        }
    }
    __syncthreads();
    const int m = g_ccount;
    const int r = sb[1];
    for (int i = t; i < m; i += 1024){
        unsigned ki = g_cand[i];
        int less = 0, eq = 0;
        for (int j = 0; j < m; j++){
            unsigned kj = g_cand[j];
            less += (kj < ki);
            eq   += (kj == ki);
        }
        if (less <= r && r < less + eq){
            float val = key2f(ki);
            out[2] = val*val;                     // loss_average
        }
    }
    __syncthreads();
    if (t == 0){
        out[0] = (float)(g_sum * (1.0/(double)TOTD));  // loss_smooth
        out[1] = __uint_as_float(g_mon);               // loss_mon
        g_sum = 0.0; g_mon = 0u; g_ccount = 0;         // reset for next replay
    }
    g_hist[4*t+0] = 0; g_hist[4*t+1] = 0; g_hist[4*t+2] = 0; g_hist[4*t+3] = 0;
}

// ---------------- launch ----------------
extern "C" void kernel_launch(void* const* d_in, const int* in_sizes, int n_in,
                              void* d_out, int out_size) {
    const float* p = (const float*)d_in[0];
    float* out = (float*)d_out;

    {
        dim3 grid(WW/TX, HH/TY, DD/ZC);   // 6 x 48 x 8 = 2304 blocks
        dim3 block(TX, TY);
        k_median<<<grid, block>>>(p);
    }
    k_post<<<1, 1024>>>(out);
}